// round 13
// baseline (speedup 1.0000x reference)
#include <cuda_runtime.h>
#include <math.h>

#define NPTS   32768          // N = B*P
#define BATCH  8
#define PPB    4096           // P
#define KNN    20             // K
#define LCOV   10             // L
#define FDIM   32             // F
#define KSV    5              // KS
#define NCLS   40
#define NROWS  24             // (N*F*3)/(P*F)

// ---------------- scratch (device globals; no allocation allowed) ----------
__device__ float4 g_pos4[NPTS];          // (x,y,z,|p|^2)
__device__ int    g_nbr[NPTS * KNN];
__device__ float  g_node[NPTS * FDIM];
__device__ float  g_v3[NPTS * 3];
__device__ float  g_stats[2 * FDIM];     // [0:32) mean, [32:64) invstd
__device__ float  g_part[4096 * 64];     // bn partials from geom blocks
__device__ float  g_ys[NROWS * FDIM];

// ======================= K0: pos4 precompute ===============================
__global__ __launch_bounds__(256) void pos4_kernel(const float* __restrict__ pos) {
    const int i = blockIdx.x * 256 + threadIdx.x;
    const float cx = pos[i * 3 + 0];
    const float cy = pos[i * 3 + 1];
    const float cz = pos[i * 3 + 2];
    const float cw = __fmaf_rn(cz, cz, __fmaf_rn(cy, cy, __fmul_rn(cx, cx)));
    g_pos4[i] = make_float4(cx, cy, cz, cw);
}

// ======================= K1: two-phase warp kNN ============================
// One warp per query. Key s = |c|^2 - 2 q.c (monotone shift of d^2); self key
// ~ -|q|^2 is the strict minimum, so we keep 21 slots and drop slot 0.
// Pass A: per (lane,round) cell (4 candidates) fold a register min; T0 = 21st
//   smallest of the 32 lane minima (bitonic) — PROVABLY >= the true 21st key
//   (>=21 lanes have a candidate <= T0), so {key <= T0} is a superset of the
//   true top-21. Zero divergence.
// Pass B: revisit only rounds with a flagged cell; flagged lanes reload their
//   4 candidates; survivors go through the distributed shfl insert chain with
//   FIXED threshold T0 (no per-insert tightening). ~35 inserts total.
__device__ __forceinline__ float knn_key(float qx, float qy, float qz, float4 c) {
    float dot = __fmaf_rn(qz, c.z, __fmaf_rn(qy, c.y, __fmul_rn(qx, c.x)));
    return __fmaf_rn(-2.0f, dot, c.w);
}

__global__ __launch_bounds__(256) void knn_kernel() {
    const int lane = threadIdx.x & 31;
    const int w    = threadIdx.x >> 5;
    const int q    = blockIdx.x * 8 + w;
    const int base = (q >> 12) << 12;           // batch * PPB

    const float4 qp = g_pos4[q];
    const float qx = qp.x, qy = qp.y, qz = qp.z;

    const float INF  = __int_as_float(0x7f800000);
    const float NINF = __int_as_float(0xff800000);
    const float4* __restrict__ bp = g_pos4 + base;

    // ---------------- pass A: per-cell minima ----------------
    float cellmin[32];
#pragma unroll
    for (int r = 0; r < 32; r++) {
        const int rb = r * 128;
        const float k0 = knn_key(qx, qy, qz, bp[rb + lane]);
        const float k1 = knn_key(qx, qy, qz, bp[rb + 32 + lane]);
        const float k2 = knn_key(qx, qy, qz, bp[rb + 64 + lane]);
        const float k3 = knn_key(qx, qy, qz, bp[rb + 96 + lane]);
        cellmin[r] = fminf(fminf(k0, k1), fminf(k2, k3));
    }
    float lmin = INF;
#pragma unroll
    for (int r = 0; r < 32; r++) lmin = fminf(lmin, cellmin[r]);

    // bitonic sort of 32 lane minima (ascending across lanes)
    float v = lmin;
#pragma unroll
    for (int k = 2; k <= 32; k <<= 1) {
#pragma unroll
        for (int j = k >> 1; j > 0; j >>= 1) {
            const float o = __shfl_xor_sync(0xffffffffu, v, j);
            const bool up    = ((lane & k) == 0);
            const bool lower = ((lane & j) == 0);
            v = (lower == up) ? fminf(v, o) : fmaxf(v, o);
        }
    }
    const float T0 = __shfl_sync(0xffffffffu, v, KNN);   // 21st smallest sample

    // ---------------- pass B: exact selection over survivors ----------------
    float bd = INF;      // distributed list: lane i = slot i
    int   bi = -1;
    for (int r = 0; r < 32; r++) {
        const bool flag = (cellmin[r] <= T0);
        if (!__any_sync(0xffffffffu, flag)) continue;
        const int rb = r * 128;
        float k0 = INF, k1 = INF, k2 = INF, k3 = INF;
        if (flag) {
            k0 = knn_key(qx, qy, qz, bp[rb + lane]);
            k1 = knn_key(qx, qy, qz, bp[rb + 32 + lane]);
            k2 = knn_key(qx, qy, qz, bp[rb + 64 + lane]);
            k3 = knn_key(qx, qy, qz, bp[rb + 96 + lane]);
        }
#pragma unroll
        for (int s = 0; s < 4; s++) {
            const float ks = (s == 0) ? k0 : (s == 1) ? k1 : (s == 2) ? k2 : k3;
            unsigned mask = __ballot_sync(0xffffffffu, ks <= T0);
            while (mask) {
                const int l = __ffs(mask) - 1;
                mask &= mask - 1;
                const float vv  = __shfl_sync(0xffffffffu, ks, l);
                const int   vid = base + rb + s * 32 + l;
                float prev   = __shfl_up_sync(0xffffffffu, bd, 1);
                int   previd = __shfl_up_sync(0xffffffffu, bi, 1);
                if (lane == 0) prev = NINF;
                const float tmax = fmaxf(vv, prev);
                const int   tmid = (vv >= prev) ? vid : previd;
                const bool  keep = (bd <= tmax);   // equal keys keep incumbent
                bi = keep ? bi : tmid;
                bd = keep ? bd : tmax;
            }
        }
    }

    // slot 0 = self; emit slots 1..20
    if (lane >= 1 && lane <= KNN) g_nbr[q * KNN + lane - 1] = bi;
}

// ======================= K2: geometry + spline conv (+ bn partials) ========
__device__ __forceinline__ void power_iter(
    float m00, float m01, float m02, float m11, float m12, float m22,
    float& vx, float& vy, float& vz, float& lam)
{
    vx = vy = vz = 0.57735026918962576f;
#pragma unroll
    for (int it = 0; it < 5; it++) {
        float wx = m00 * vx + m01 * vy + m02 * vz;
        float wy = m01 * vx + m11 * vy + m12 * vz;
        float wz = m02 * vx + m12 * vy + m22 * vz;
        float nr = sqrtf(wx * wx + wy * wy + wz * wz) + 1e-12f;
        vx = wx / nr; vy = wy / nr; vz = wz / nr;
    }
    float wx = m00 * vx + m01 * vy + m02 * vz;
    float wy = m01 * vx + m11 * vy + m12 * vz;
    float wz = m02 * vx + m12 * vy + m22 * vz;
    lam = vx * wx + vy * wy + vz * wz;
}

// warp per point; 8 warps (8 points) per block
__global__ __launch_bounds__(256) void geom_kernel(
    const float* __restrict__ pos, const float* __restrict__ Wsp,
    const float* __restrict__ root, const float* __restrict__ bias)
{
    __shared__ float  wspS[125 * 32];
    __shared__ float  clusS[8][KNN][3];
    __shared__ float2 bfS[8][KNN * 8];     // (basis, flat-as-float)
    __shared__ float  bnS[8][32], bn2S[8][32];

    const int tid  = threadIdx.x;
    const int w    = tid >> 5;
    const int lane = tid & 31;
    const int n    = blockIdx.x * 8 + w;

    for (int i = tid; i < 125 * 32; i += 256) wspS[i] = Wsp[i];

    const float px = pos[n * 3 + 0];
    const float py = pos[n * 3 + 1];
    const float pz = pos[n * 3 + 2];

    if (lane < KNN) {
        const int j = g_nbr[n * KNN + lane];
        clusS[w][lane][0] = pos[j * 3 + 0] - px;
        clusS[w][lane][1] = pos[j * 3 + 1] - py;
        clusS[w][lane][2] = pos[j * 3 + 2] - pz;
    }
    __syncthreads();   // covers wspS load + cluster writes

    // covariance over first LCOV neighbors (redundant per lane; smem broadcast)
    float m00 = 0, m01 = 0, m02 = 0, m11 = 0, m12 = 0, m22 = 0;
#pragma unroll
    for (int k = 0; k < LCOV; k++) {
        const float x = clusS[w][k][0], y = clusS[w][k][1], z = clusS[w][k][2];
        m00 += x * x; m01 += x * y; m02 += x * z;
        m11 += y * y; m12 += y * z; m22 += z * z;
    }

    float e1x, e1y, e1z, lam1;
    power_iter(m00, m01, m02, m11, m12, m22, e1x, e1y, e1z, lam1);
    // deflate
    float a00 = m00 - lam1 * e1x * e1x;
    float a01 = m01 - lam1 * e1x * e1y;
    float a02 = m02 - lam1 * e1x * e1z;
    float a11 = m11 - lam1 * e1y * e1y;
    float a12 = m12 - lam1 * e1y * e1z;
    float a22 = m22 - lam1 * e1z * e1z;
    float e2x, e2y, e2z, lam2;
    power_iter(a00, a01, a02, a11, a12, a22, e2x, e2y, e2z, lam2);
    // v3 = cross(v1, v2), normalized
    float e3x = e1y * e2z - e1z * e2y;
    float e3y = e1z * e2x - e1x * e2z;
    float e3z = e1x * e2y - e1y * e2x;
    {
        float nr = sqrtf(e3x * e3x + e3y * e3y + e3z * e3z) + 1e-12f;
        e3x /= nr; e3y /= nr; e3z /= nr;
    }

    // pass over all K: sign accumulator and max|dirc|
    float sum2 = 0.f, mx01 = 0.f, mx2 = 0.f;
#pragma unroll
    for (int k = 0; k < KNN; k++) {
        const float x = clusS[w][k][0], y = clusS[w][k][1], z = clusS[w][k][2];
        const float d0 = x * e1x + y * e1y + z * e1z;
        const float d1 = x * e2x + y * e2y + z * e2z;
        const float d2 = x * e3x + y * e3y + z * e3z;
        sum2 += d2;
        mx01 = fmaxf(mx01, fmaxf(fabsf(d0), fabsf(d1)));
        mx2  = fmaxf(mx2, fabsf(d2));
    }
    const float sgn = (sum2 > 0.f) ? 1.f : ((sum2 < 0.f) ? -1.f : 0.f);
    const float mx  = fmaxf(mx01, (sgn != 0.f) ? mx2 : 0.f);

    // spline basis per neighbor (lane k handles neighbor k)
    if (lane < KNN) {
        const float x = clusS[w][lane][0], y = clusS[w][lane][1], z = clusS[w][lane][2];
        const float d0 = x * e1x + y * e1y + z * e1z;
        const float d1 = x * e2x + y * e2y + z * e2z;
        const float d2 = (x * e3x + y * e3y + z * e3z) * sgn;
        const float p0 = d0 / mx * 0.5f + 0.5f;
        const float p1 = d1 / mx * 0.5f + 0.5f;
        const float p2 = d2 / mx * 0.5f + 0.5f;
        const float v0 = p0 * 4.f, v1 = p1 * 4.f, v2 = p2 * 4.f;
        const float f0 = floorf(v0), f1 = floorf(v1), f2 = floorf(v2);
        const float r0 = v0 - f0, r1 = v1 - f1, r2 = v2 - f2;
        const int   i0 = (int)f0, i1 = (int)f1, i2 = (int)f2;
#pragma unroll
        for (int s = 0; s < 8; s++) {
            const int b0 = (s >> 2) & 1, b1v = (s >> 1) & 1, b2v = s & 1;
            const int c0 = min(max(i0 + b0, 0), KSV - 1);
            const int c1 = min(max(i1 + b1v, 0), KSV - 1);
            const int c2 = min(max(i2 + b2v, 0), KSV - 1);
            const float wgt = (b0 ? r0 : 1.f - r0) * (b1v ? r1 : 1.f - r1) * (b2v ? r2 : 1.f - r2);
            const int flat = (c0 * KSV + c1) * KSV + c2;
            bfS[w][lane * 8 + s] = make_float2(wgt, __int_as_float(flat));
        }
    }
    __syncwarp();

    // lane = feature f: accumulate msg over 160 (neighbor,corner) pairs
    float acc = 0.f;
#pragma unroll 8
    for (int e = 0; e < KNN * 8; e++) {
        const float2 t = bfS[w][e];
        acc = fmaf(t.x, wspS[__float_as_int(t.y) * 32 + lane], acc);
    }
    const float nodev = acc / 20.0f + root[lane] + bias[lane];
    g_node[n * FDIM + lane] = nodev;
    bnS[w][lane]  = nodev;
    bn2S[w][lane] = nodev * nodev;
    if (lane == 0) {
        g_v3[n * 3 + 0] = e3x;
        g_v3[n * 3 + 1] = e3y;
        g_v3[n * 3 + 2] = e3z;
    }

    // block bn partials (deterministic fixed-order sums)
    __syncthreads();
    if (tid < 64) {
        const int f  = tid & 31;
        const bool sq = (tid >= 32);
        float s = 0.f;
#pragma unroll
        for (int ww = 0; ww < 8; ww++) s += sq ? bn2S[ww][f] : bnS[ww][f];
        g_part[blockIdx.x * 64 + tid] = s;
    }
}

// ======================= K3: bn reduce (32 blocks, double accum) ===========
__global__ __launch_bounds__(256) void bnr_kernel() {
    __shared__ double sD[256], s2D[256];
    const int f = blockIdx.x;               // feature
    const int tid = threadIdx.x;
    double s = 0.0, s2 = 0.0;
    for (int b = tid; b < 4096; b += 256) {
        s  += (double)g_part[b * 64 + f];
        s2 += (double)g_part[b * 64 + 32 + f];
    }
    sD[tid] = s; s2D[tid] = s2; __syncthreads();
    for (int o = 128; o > 0; o >>= 1) {
        if (tid < o) { sD[tid] += sD[tid + o]; s2D[tid] += s2D[tid + o]; }
        __syncthreads();
    }
    if (tid == 0) {
        const double mu  = sD[0] / (double)NPTS;
        const double ex2 = s2D[0] / (double)NPTS;
        const double var = ex2 - mu * mu;
        g_stats[f]        = (float)mu;
        g_stats[FDIM + f] = (float)(1.0 / sqrt(var + 1e-5));
    }
}

// ======================= K4: scrambled sigmoid mean -> ys ==================
__global__ __launch_bounds__(256) void ys_kernel(
    const float* __restrict__ gamma, const float* __restrict__ beta)
{
    __shared__ float red[256];
    const int r = blockIdx.x >> 5;
    const int f2 = blockIdx.x & 31;
    const int tid = threadIdx.x;
    float s = 0.f;
    for (int p = tid; p < PPB; p += 256) {
        const int linear = r * (PPB * FDIM) + p * FDIM + f2;
        const int n   = linear / 96;
        const int rem = linear - n * 96;
        const int f   = rem / 3;
        const int c   = rem - f * 3;
        const float x  = g_node[n * FDIM + f];
        const float xb = gamma[f] * (x - g_stats[f]) * g_stats[FDIM + f] + beta[f];
        const float z  = xb * g_v3[n * 3 + c];
        s += 1.0f / (1.0f + expf(-z));
    }
    red[tid] = s; __syncthreads();
    for (int o = 128; o > 0; o >>= 1) { if (tid < o) red[tid] += red[tid + o]; __syncthreads(); }
    if (tid == 0) g_ys[blockIdx.x] = red[0] / (float)PPB;
}

// ======================= K5: fused MLP + log_softmax (block per row) =======
__global__ __launch_bounds__(256) void mlp_kernel(
    const float* __restrict__ W1, const float* __restrict__ b1,
    const float* __restrict__ W2, const float* __restrict__ b2,
    float* __restrict__ out)
{
    __shared__ float ysS[FDIM];
    __shared__ float hS[256];
    __shared__ float lg[NCLS];
    const int r = blockIdx.x, tid = threadIdx.x;

    if (tid < FDIM) ysS[tid] = g_ys[r * FDIM + tid];
    __syncthreads();

    {   // hidden unit j = tid
        float a = b1[tid];
#pragma unroll
        for (int f = 0; f < FDIM; f++) a = fmaf(ysS[f], W1[f * 256 + tid], a);
        hS[tid] = (a > 0.f) ? a : expm1f(a);
    }
    __syncthreads();

    if (tid < NCLS) {
        float a = b2[tid];
#pragma unroll 8
        for (int j = 0; j < 256; j++) a = fmaf(hS[j], W2[j * NCLS + tid], a);
        lg[tid] = a;
    }
    __syncthreads();

    if (tid < 32) {
        const float a = lg[tid];
        const float b = (tid < NCLS - 32) ? lg[32 + tid] : -__int_as_float(0x7f800000);
        float m = fmaxf(a, b);
#pragma unroll
        for (int o = 16; o > 0; o >>= 1) m = fmaxf(m, __shfl_xor_sync(0xffffffffu, m, o));
        float s = expf(a - m) + ((tid < NCLS - 32) ? expf(b - m) : 0.f);
#pragma unroll
        for (int o = 16; o > 0; o >>= 1) s += __shfl_xor_sync(0xffffffffu, s, o);
        const float ls = logf(s);
        out[r * NCLS + tid] = a - m - ls;
        if (tid < NCLS - 32) out[r * NCLS + 32 + tid] = b - m - ls;
    }
}

// ======================= launch ============================================
extern "C" void kernel_launch(void* const* d_in, const int* in_sizes, int n_in,
                              void* d_out, int out_size) {
    const float* pos   = (const float*)d_in[0];
    const float* Wsp   = (const float*)d_in[1];
    const float* root  = (const float*)d_in[2];
    const float* bias  = (const float*)d_in[3];
    const float* gamma = (const float*)d_in[4];
    const float* beta  = (const float*)d_in[5];
    const float* W1    = (const float*)d_in[6];
    const float* b1    = (const float*)d_in[7];
    const float* W2    = (const float*)d_in[8];
    const float* b2    = (const float*)d_in[9];
    float* out = (float*)d_out;

    pos4_kernel<<<NPTS / 256, 256>>>(pos);
    knn_kernel<<<NPTS / 8, 256>>>();
    geom_kernel<<<NPTS / 8, 256>>>(pos, Wsp, root, bias);
    bnr_kernel<<<FDIM, 256>>>();
    ys_kernel<<<NROWS * FDIM, 256>>>(gamma, beta);
    mlp_kernel<<<NROWS, 256>>>(W1, b1, W2, b2, out);
}

// round 16
// speedup vs baseline: 1.7423x; 1.7423x over previous
#include <cuda_runtime.h>
#include <math.h>

#define NPTS   32768          // N = B*P
#define BATCH  8
#define PPB    4096           // P
#define KNN    20             // K
#define LCOV   10             // L
#define FDIM   32             // F
#define KSV    5              // KS
#define NCLS   40
#define NROWS  24             // (N*F*3)/(P*F)

// ---------------- scratch (device globals; no allocation allowed) ----------
__device__ float4 g_pos4[NPTS];          // (x,y,z,|p|^2)
__device__ int    g_nbr[NPTS * KNN];
__device__ float  g_node[NPTS * FDIM];
__device__ float  g_v3[NPTS * 3];
__device__ float  g_stats[2 * FDIM];     // [0:32) mean, [32:64) invstd
__device__ float  g_part[64 * 4096];     // bn partials, TRANSPOSED: row=quantity
__device__ float  g_ys[NROWS * FDIM];

// ======================= K0: pos4 precompute ===============================
__global__ __launch_bounds__(256) void pos4_kernel(const float* __restrict__ pos) {
    const int i = blockIdx.x * 256 + threadIdx.x;
    const float cx = pos[i * 3 + 0];
    const float cy = pos[i * 3 + 1];
    const float cz = pos[i * 3 + 2];
    const float cw = __fmaf_rn(cz, cz, __fmaf_rn(cy, cy, __fmul_rn(cx, cx)));
    g_pos4[i] = make_float4(cx, cy, cz, cw);
}

// ======================= K1: two-phase warp kNN (tight sample) =============
// One warp per query. Key s = |c|^2 - 2 q.c (monotone shift of d^2); self key
// ~ -|q|^2 is the strict minimum (slot 0, dropped at the end).
// Pass A: scan all 4096 candidates; per lane keep (m1,m2) = its two smallest
//   keys (unconditional FMNMX, no divergence) and cellmin[r] per round.
// Threshold: T = 21st smallest of the 64 sampled keys {m1,m2}. Valid (21st of
//   a sub-multiset >= global 21st => survivors superset of top-21) and tight
//   (exact unless a lane holds >=3 of the true top-21; then ~23rd key).
// Pass B: only flagged (cellmin<=T) lanes/rounds reload (~2KB); survivors go
//   through the exact distributed shfl insert chain in ascending index order
//   (equal keys keep incumbent => jax top_k tie stability).
__device__ __forceinline__ float knn_key(float qx, float qy, float qz, float4 c) {
    float dot = __fmaf_rn(qz, c.z, __fmaf_rn(qy, c.y, __fmul_rn(qx, c.x)));
    return __fmaf_rn(-2.0f, dot, c.w);
}

// ascending bitonic sort of one value per lane (standard XOR network)
__device__ __forceinline__ float warp_bitonic_sort(float v, int lane) {
#pragma unroll
    for (int k = 2; k <= 32; k <<= 1) {
#pragma unroll
        for (int j = k >> 1; j > 0; j >>= 1) {
            const float o = __shfl_xor_sync(0xffffffffu, v, j);
            const bool up    = ((lane & k) == 0);
            const bool lower = ((lane & j) == 0);
            v = (lower == up) ? fminf(v, o) : fmaxf(v, o);
        }
    }
    return v;
}

__global__ __launch_bounds__(256) void knn_kernel() {
    const int lane = threadIdx.x & 31;
    const int w    = threadIdx.x >> 5;
    const int q    = blockIdx.x * 8 + w;
    const int base = (q >> 12) << 12;           // batch * PPB

    const float4 qp = g_pos4[q];
    const float qx = qp.x, qy = qp.y, qz = qp.z;

    const float INF  = __int_as_float(0x7f800000);
    const float NINF = __int_as_float(0xff800000);
    const float4* __restrict__ bp = g_pos4 + base;

    // ---------------- pass A: per-lane top-2 + per-cell minima ----------------
    float cellmin[32];
    float m1 = INF, m2 = INF;
#pragma unroll
    for (int r = 0; r < 32; r++) {
        const int rb = r * 128;
        const float k0 = knn_key(qx, qy, qz, bp[rb + lane]);
        const float k1 = knn_key(qx, qy, qz, bp[rb + 32 + lane]);
        const float k2 = knn_key(qx, qy, qz, bp[rb + 64 + lane]);
        const float k3 = knn_key(qx, qy, qz, bp[rb + 96 + lane]);
        // per-lane 2-smallest (dependency-light FMNMX chain)
        m2 = fminf(m2, fmaxf(k0, m1)); m1 = fminf(m1, k0);
        m2 = fminf(m2, fmaxf(k1, m1)); m1 = fminf(m1, k1);
        m2 = fminf(m2, fmaxf(k2, m1)); m1 = fminf(m1, k2);
        m2 = fminf(m2, fmaxf(k3, m1)); m1 = fminf(m1, k3);
        cellmin[r] = fminf(fminf(k0, k1), fminf(k2, k3));
    }

    // ---------------- threshold: 21st smallest of the 64 samples -------------
    const float a = warp_bitonic_sort(m1, lane);        // ascending
    const float b = warp_bitonic_sort(m2, lane);        // ascending
    const float brev = __shfl_sync(0xffffffffu, b, 31 - lane);
    float lo = fminf(a, brev);                          // 32 smallest, bitonic
#pragma unroll
    for (int j = 16; j > 0; j >>= 1) {                  // bitonic cleanup
        const float o = __shfl_xor_sync(0xffffffffu, lo, j);
        lo = ((lane & j) == 0) ? fminf(lo, o) : fmaxf(lo, o);
    }
    const float T = __shfl_sync(0xffffffffu, lo, KNN);  // sample 21st smallest

    // ---------------- pass B: exact selection over survivors ----------------
    float bd = INF;      // distributed list: lane i = slot i
    int   bi = -1;
    for (int r = 0; r < 32; r++) {
        const bool flag = (cellmin[r] <= T);
        if (!__any_sync(0xffffffffu, flag)) continue;
        const int rb = r * 128;
        float k0 = INF, k1 = INF, k2 = INF, k3 = INF;
        if (flag) {
            k0 = knn_key(qx, qy, qz, bp[rb + lane]);
            k1 = knn_key(qx, qy, qz, bp[rb + 32 + lane]);
            k2 = knn_key(qx, qy, qz, bp[rb + 64 + lane]);
            k3 = knn_key(qx, qy, qz, bp[rb + 96 + lane]);
        }
#pragma unroll
        for (int s = 0; s < 4; s++) {
            const float ks = (s == 0) ? k0 : (s == 1) ? k1 : (s == 2) ? k2 : k3;
            unsigned mask = __ballot_sync(0xffffffffu, ks <= T);
            while (mask) {
                const int l = __ffs(mask) - 1;
                mask &= mask - 1;
                const float vv  = __shfl_sync(0xffffffffu, ks, l);
                const int   vid = base + rb + s * 32 + l;
                float prev   = __shfl_up_sync(0xffffffffu, bd, 1);
                int   previd = __shfl_up_sync(0xffffffffu, bi, 1);
                if (lane == 0) prev = NINF;
                const float tmax = fmaxf(vv, prev);
                const int   tmid = (vv >= prev) ? vid : previd;
                const bool  keep = (bd <= tmax);   // equal keys keep incumbent
                bi = keep ? bi : tmid;
                bd = keep ? bd : tmax;
            }
        }
    }

    // slot 0 = self; emit slots 1..20
    if (lane >= 1 && lane <= KNN) g_nbr[q * KNN + lane - 1] = bi;
}

// ======================= K2: geometry + spline conv (+ bn partials) ========
__device__ __forceinline__ void power_iter(
    float m00, float m01, float m02, float m11, float m12, float m22,
    float& vx, float& vy, float& vz, float& lam)
{
    vx = vy = vz = 0.57735026918962576f;
#pragma unroll
    for (int it = 0; it < 5; it++) {
        float wx = m00 * vx + m01 * vy + m02 * vz;
        float wy = m01 * vx + m11 * vy + m12 * vz;
        float wz = m02 * vx + m12 * vy + m22 * vz;
        float nr = sqrtf(wx * wx + wy * wy + wz * wz) + 1e-12f;
        vx = wx / nr; vy = wy / nr; vz = wz / nr;
    }
    float wx = m00 * vx + m01 * vy + m02 * vz;
    float wy = m01 * vx + m11 * vy + m12 * vz;
    float wz = m02 * vx + m12 * vy + m22 * vz;
    lam = vx * wx + vy * wy + vz * wz;
}

// warp per point; 8 warps (8 points) per block
__global__ __launch_bounds__(256) void geom_kernel(
    const float* __restrict__ pos, const float* __restrict__ Wsp,
    const float* __restrict__ root, const float* __restrict__ bias)
{
    __shared__ float  wspS[125 * 32];
    __shared__ float  clusS[8][KNN][3];
    __shared__ float2 bfS[8][KNN * 8];     // (basis, flat-as-float)
    __shared__ float  bnS[8][32], bn2S[8][32];

    const int tid  = threadIdx.x;
    const int w    = tid >> 5;
    const int lane = tid & 31;
    const int n    = blockIdx.x * 8 + w;

    for (int i = tid; i < 125 * 32; i += 256) wspS[i] = Wsp[i];

    const float px = pos[n * 3 + 0];
    const float py = pos[n * 3 + 1];
    const float pz = pos[n * 3 + 2];

    if (lane < KNN) {
        const int j = g_nbr[n * KNN + lane];
        clusS[w][lane][0] = pos[j * 3 + 0] - px;
        clusS[w][lane][1] = pos[j * 3 + 1] - py;
        clusS[w][lane][2] = pos[j * 3 + 2] - pz;
    }
    __syncthreads();   // covers wspS load + cluster writes

    // covariance over first LCOV neighbors (redundant per lane; smem broadcast)
    float m00 = 0, m01 = 0, m02 = 0, m11 = 0, m12 = 0, m22 = 0;
#pragma unroll
    for (int k = 0; k < LCOV; k++) {
        const float x = clusS[w][k][0], y = clusS[w][k][1], z = clusS[w][k][2];
        m00 += x * x; m01 += x * y; m02 += x * z;
        m11 += y * y; m12 += y * z; m22 += z * z;
    }

    float e1x, e1y, e1z, lam1;
    power_iter(m00, m01, m02, m11, m12, m22, e1x, e1y, e1z, lam1);
    // deflate
    float a00 = m00 - lam1 * e1x * e1x;
    float a01 = m01 - lam1 * e1x * e1y;
    float a02 = m02 - lam1 * e1x * e1z;
    float a11 = m11 - lam1 * e1y * e1y;
    float a12 = m12 - lam1 * e1y * e1z;
    float a22 = m22 - lam1 * e1z * e1z;
    float e2x, e2y, e2z, lam2;
    power_iter(a00, a01, a02, a11, a12, a22, e2x, e2y, e2z, lam2);
    // v3 = cross(v1, v2), normalized
    float e3x = e1y * e2z - e1z * e2y;
    float e3y = e1z * e2x - e1x * e2z;
    float e3z = e1x * e2y - e1y * e2x;
    {
        float nr = sqrtf(e3x * e3x + e3y * e3y + e3z * e3z) + 1e-12f;
        e3x /= nr; e3y /= nr; e3z /= nr;
    }

    // pass over all K: sign accumulator and max|dirc|
    float sum2 = 0.f, mx01 = 0.f, mx2 = 0.f;
#pragma unroll
    for (int k = 0; k < KNN; k++) {
        const float x = clusS[w][k][0], y = clusS[w][k][1], z = clusS[w][k][2];
        const float d0 = x * e1x + y * e1y + z * e1z;
        const float d1 = x * e2x + y * e2y + z * e2z;
        const float d2 = x * e3x + y * e3y + z * e3z;
        sum2 += d2;
        mx01 = fmaxf(mx01, fmaxf(fabsf(d0), fabsf(d1)));
        mx2  = fmaxf(mx2, fabsf(d2));
    }
    const float sgn = (sum2 > 0.f) ? 1.f : ((sum2 < 0.f) ? -1.f : 0.f);
    const float mx  = fmaxf(mx01, (sgn != 0.f) ? mx2 : 0.f);

    // spline basis per neighbor (lane k handles neighbor k)
    if (lane < KNN) {
        const float x = clusS[w][lane][0], y = clusS[w][lane][1], z = clusS[w][lane][2];
        const float d0 = x * e1x + y * e1y + z * e1z;
        const float d1 = x * e2x + y * e2y + z * e2z;
        const float d2 = (x * e3x + y * e3y + z * e3z) * sgn;
        const float p0 = d0 / mx * 0.5f + 0.5f;
        const float p1 = d1 / mx * 0.5f + 0.5f;
        const float p2 = d2 / mx * 0.5f + 0.5f;
        const float v0 = p0 * 4.f, v1 = p1 * 4.f, v2 = p2 * 4.f;
        const float f0 = floorf(v0), f1 = floorf(v1), f2 = floorf(v2);
        const float r0 = v0 - f0, r1 = v1 - f1, r2 = v2 - f2;
        const int   i0 = (int)f0, i1 = (int)f1, i2 = (int)f2;
#pragma unroll
        for (int s = 0; s < 8; s++) {
            const int b0 = (s >> 2) & 1, b1v = (s >> 1) & 1, b2v = s & 1;
            const int c0 = min(max(i0 + b0, 0), KSV - 1);
            const int c1 = min(max(i1 + b1v, 0), KSV - 1);
            const int c2 = min(max(i2 + b2v, 0), KSV - 1);
            const float wgt = (b0 ? r0 : 1.f - r0) * (b1v ? r1 : 1.f - r1) * (b2v ? r2 : 1.f - r2);
            const int flat = (c0 * KSV + c1) * KSV + c2;
            bfS[w][lane * 8 + s] = make_float2(wgt, __int_as_float(flat));
        }
    }
    __syncwarp();

    // lane = feature f: accumulate msg over 160 (neighbor,corner) pairs
    float acc = 0.f;
#pragma unroll 8
    for (int e = 0; e < KNN * 8; e++) {
        const float2 t = bfS[w][e];
        acc = fmaf(t.x, wspS[__float_as_int(t.y) * 32 + lane], acc);
    }
    const float nodev = acc / 20.0f + root[lane] + bias[lane];
    g_node[n * FDIM + lane] = nodev;
    bnS[w][lane]  = nodev;
    bn2S[w][lane] = nodev * nodev;
    if (lane == 0) {
        g_v3[n * 3 + 0] = e3x;
        g_v3[n * 3 + 1] = e3y;
        g_v3[n * 3 + 2] = e3z;
    }

    // block bn partials, TRANSPOSED layout: g_part[row * 4096 + block]
    __syncthreads();
    if (tid < 64) {
        const int f  = tid & 31;
        const bool sq = (tid >= 32);
        float s = 0.f;
#pragma unroll
        for (int ww = 0; ww < 8; ww++) s += sq ? bn2S[ww][f] : bnS[ww][f];
        g_part[tid * 4096 + blockIdx.x] = s;
    }
}

// ======================= K3: bn reduce (32 blocks, contiguous rows) ========
__global__ __launch_bounds__(256) void bnr_kernel() {
    __shared__ double sD[256], s2D[256];
    const int f = blockIdx.x;               // feature
    const int tid = threadIdx.x;
    double s = 0.0, s2 = 0.0;
#pragma unroll 4
    for (int b = tid; b < 4096; b += 256) {
        s  += (double)g_part[f * 4096 + b];
        s2 += (double)g_part[(f + 32) * 4096 + b];
    }
    sD[tid] = s; s2D[tid] = s2; __syncthreads();
    for (int o = 128; o > 0; o >>= 1) {
        if (tid < o) { sD[tid] += sD[tid + o]; s2D[tid] += s2D[tid + o]; }
        __syncthreads();
    }
    if (tid == 0) {
        const double mu  = sD[0] / (double)NPTS;
        const double ex2 = s2D[0] / (double)NPTS;
        const double var = ex2 - mu * mu;
        g_stats[f]        = (float)mu;
        g_stats[FDIM + f] = (float)(1.0 / sqrt(var + 1e-5));
    }
}

// ======================= K4: scrambled sigmoid mean -> ys ==================
__global__ __launch_bounds__(256) void ys_kernel(
    const float* __restrict__ gamma, const float* __restrict__ beta)
{
    __shared__ float red[256];
    const int r = blockIdx.x >> 5;
    const int f2 = blockIdx.x & 31;
    const int tid = threadIdx.x;
    float s = 0.f;
    for (int p = tid; p < PPB; p += 256) {
        const int linear = r * (PPB * FDIM) + p * FDIM + f2;
        const int n   = linear / 96;
        const int rem = linear - n * 96;
        const int f   = rem / 3;
        const int c   = rem - f * 3;
        const float x  = g_node[n * FDIM + f];
        const float xb = gamma[f] * (x - g_stats[f]) * g_stats[FDIM + f] + beta[f];
        const float z  = xb * g_v3[n * 3 + c];
        s += 1.0f / (1.0f + expf(-z));
    }
    red[tid] = s; __syncthreads();
    for (int o = 128; o > 0; o >>= 1) { if (tid < o) red[tid] += red[tid + o]; __syncthreads(); }
    if (tid == 0) g_ys[blockIdx.x] = red[0] / (float)PPB;
}

// ======================= K5: fused MLP + log_softmax (block per row) =======
__global__ __launch_bounds__(256) void mlp_kernel(
    const float* __restrict__ W1, const float* __restrict__ b1,
    const float* __restrict__ W2, const float* __restrict__ b2,
    float* __restrict__ out)
{
    __shared__ float ysS[FDIM];
    __shared__ float hS[256];
    __shared__ float lg[NCLS];
    const int r = blockIdx.x, tid = threadIdx.x;

    if (tid < FDIM) ysS[tid] = g_ys[r * FDIM + tid];
    __syncthreads();

    {   // hidden unit j = tid
        float a = b1[tid];
#pragma unroll
        for (int f = 0; f < FDIM; f++) a = fmaf(ysS[f], W1[f * 256 + tid], a);
        hS[tid] = (a > 0.f) ? a : expm1f(a);
    }
    __syncthreads();

    if (tid < NCLS) {
        float a = b2[tid];
#pragma unroll 8
        for (int j = 0; j < 256; j++) a = fmaf(hS[j], W2[j * NCLS + tid], a);
        lg[tid] = a;
    }
    __syncthreads();

    if (tid < 32) {
        const float a = lg[tid];
        const float b = (tid < NCLS - 32) ? lg[32 + tid] : -__int_as_float(0x7f800000);
        float m = fmaxf(a, b);
#pragma unroll
        for (int o = 16; o > 0; o >>= 1) m = fmaxf(m, __shfl_xor_sync(0xffffffffu, m, o));
        float s = expf(a - m) + ((tid < NCLS - 32) ? expf(b - m) : 0.f);
#pragma unroll
        for (int o = 16; o > 0; o >>= 1) s += __shfl_xor_sync(0xffffffffu, s, o);
        const float ls = logf(s);
        out[r * NCLS + tid] = a - m - ls;
        if (tid < NCLS - 32) out[r * NCLS + 32 + tid] = b - m - ls;
    }
}

// ======================= launch ============================================
extern "C" void kernel_launch(void* const* d_in, const int* in_sizes, int n_in,
                              void* d_out, int out_size) {
    const float* pos   = (const float*)d_in[0];
    const float* Wsp   = (const float*)d_in[1];
    const float* root  = (const float*)d_in[2];
    const float* bias  = (const float*)d_in[3];
    const float* gamma = (const float*)d_in[4];
    const float* beta  = (const float*)d_in[5];
    const float* W1    = (const float*)d_in[6];
    const float* b1    = (const float*)d_in[7];
    const float* W2    = (const float*)d_in[8];
    const float* b2    = (const float*)d_in[9];
    float* out = (float*)d_out;

    pos4_kernel<<<NPTS / 256, 256>>>(pos);
    knn_kernel<<<NPTS / 8, 256>>>();
    geom_kernel<<<NPTS / 8, 256>>>(pos, Wsp, root, bias);
    bnr_kernel<<<FDIM, 256>>>();
    ys_kernel<<<NROWS * FDIM, 256>>>(gamma, beta);
    mlp_kernel<<<NROWS, 256>>>(W1, b1, W2, b2, out);
}